// round 7
// baseline (speedup 1.0000x reference)
#include <cuda_runtime.h>
#include <cuda_bf16.h>
#include <cstdint>

#define F_IN 128
#define F_OUT 64
#define MAX_NODES 50000

// Scratch (no runtime allocation allowed)
__device__ float g_hw[(size_t)MAX_NODES * F_OUT]; // h @ (W0+W1), [N][64]

// Packed f32x2 FMA (Blackwell): d = a*b + c on 2 floats per reg
#define FMA_F32X2(d, a, b, c) \
    asm("fma.rn.f32x2 %0, %1, %2, %3;" : "=l"(d) : "l"(a), "l"(b), "l"(c))
#define PACK_DUP_F32X2(d, s) \
    asm("mov.b64 %0, {%1, %1};" : "=l"(d) : "f"(s))
#define UNPACK_F32X2(lo, hi, s) \
    asm("mov.b64 {%0, %1}, %2;" : "=f"(lo), "=f"(hi) : "l"(s))

// ---------------------------------------------------------------------------
// Kernel 1: fused GEMM + bias-init, f32x2 packed-FMA with transposed A tile.
//   g_hw[N,64] = h[N,128] @ (W0+W1) ;  out[N,64] = bias
// Tile: 64 rows x 64 cols per block, 128 threads, 8 rows x 4 cols per thread.
// A row-pairs are contiguous in hs_t -> loaded as native f32x2 pairs;
// only the 4 B scalars per k need dup-packing (4 packs per 16 FFMA2).
// All smem arrays are explicitly 16B-aligned: every vector LDS/STS below is
// provably aligned (row stride 272B = 17*16, offsets multiples of 16B).
// ---------------------------------------------------------------------------
#define GR 64
#define KC 32
#define HP 68   // hs_t row stride in floats: 272B = 16B-multiple, odd-ish banking
__global__ void __launch_bounds__(128) gemm_init_kernel(
        const float* __restrict__ h,
        const float* __restrict__ w,
        const float* __restrict__ bias,
        float* __restrict__ out,
        int n_nodes) {
    __shared__ __align__(16) float ws[KC][F_OUT];     // 8 KB (one k-chunk of W0+W1)
    __shared__ __align__(16) float hs_t[F_IN][HP];    // 34.8 KB, transposed: [k][row]
    __shared__ __align__(16) float bs[F_OUT];

    int tid = threadIdx.x;  // 128 threads
    int row0 = blockIdx.x * GR;

    if (tid < F_OUT) bs[tid] = bias[tid];

    // Load h tile transposed: 64 rows x 32 float4
    #pragma unroll
    for (int i = tid; i < GR * (F_IN / 4); i += 128) {
        int r = i >> 5;          // row within tile (0..63)
        int c = i & 31;          // float4 index along k
        float4 v = make_float4(0.f, 0.f, 0.f, 0.f);
        if (row0 + r < n_nodes)
            v = ((const float4*)(h + (size_t)(row0 + r) * F_IN))[c];
        hs_t[4 * c + 0][r] = v.x;
        hs_t[4 * c + 1][r] = v.y;
        hs_t[4 * c + 2][r] = v.z;
        hs_t[4 * c + 3][r] = v.w;
    }

    int tx = tid & 15;   // col group: cols [4*tx, 4*tx+3]
    int ty = tid >> 4;   // row group: rows [8*ty, 8*ty+7]

    // acc2[p][c]: packed (row 8ty+2p, row 8ty+2p+1) for col 4tx+c
    unsigned long long acc2[4][4];
    #pragma unroll
    for (int p = 0; p < 4; p++)
        #pragma unroll
        for (int c = 0; c < 4; c++) PACK_DUP_F32X2(acc2[p][c], 0.0f);

    #pragma unroll
    for (int kk = 0; kk < F_IN; kk += KC) {
        __syncthreads();   // (first iter: covers hs_t/bs; later: ws consumers done)
        // Stage this k-chunk of W0+W1: KC*F_OUT/4 = 512 float4
        {
            const float4* w0 = (const float4*)(w + kk * F_OUT);
            const float4* w1 = (const float4*)(w + F_IN * F_OUT + kk * F_OUT);
            float4* ws4 = (float4*)ws;
            #pragma unroll
            for (int i = tid; i < KC * F_OUT / 4; i += 128) {
                float4 a = w0[i], b = w1[i];
                ws4[i] = make_float4(a.x + b.x, a.y + b.y, a.z + b.z, a.w + b.w);
            }
        }
        __syncthreads();

        #pragma unroll 8
        for (int k = 0; k < KC; k++) {
            // 8 contiguous row values = 4 native f32x2 pairs (16B-aligned LDS.128 x2)
            ulonglong2 a01 = *(const ulonglong2*)&hs_t[kk + k][8 * ty];
            ulonglong2 a23 = *(const ulonglong2*)&hs_t[kk + k][8 * ty + 4];
            float4 bq = *(const float4*)&ws[k][4 * tx];
            unsigned long long b0, b1, b2, b3;
            PACK_DUP_F32X2(b0, bq.x);
            PACK_DUP_F32X2(b1, bq.y);
            PACK_DUP_F32X2(b2, bq.z);
            PACK_DUP_F32X2(b3, bq.w);
            FMA_F32X2(acc2[0][0], a01.x, b0, acc2[0][0]);
            FMA_F32X2(acc2[0][1], a01.x, b1, acc2[0][1]);
            FMA_F32X2(acc2[0][2], a01.x, b2, acc2[0][2]);
            FMA_F32X2(acc2[0][3], a01.x, b3, acc2[0][3]);
            FMA_F32X2(acc2[1][0], a01.y, b0, acc2[1][0]);
            FMA_F32X2(acc2[1][1], a01.y, b1, acc2[1][1]);
            FMA_F32X2(acc2[1][2], a01.y, b2, acc2[1][2]);
            FMA_F32X2(acc2[1][3], a01.y, b3, acc2[1][3]);
            FMA_F32X2(acc2[2][0], a23.x, b0, acc2[2][0]);
            FMA_F32X2(acc2[2][1], a23.x, b1, acc2[2][1]);
            FMA_F32X2(acc2[2][2], a23.x, b2, acc2[2][2]);
            FMA_F32X2(acc2[2][3], a23.x, b3, acc2[2][3]);
            FMA_F32X2(acc2[3][0], a23.y, b0, acc2[3][0]);
            FMA_F32X2(acc2[3][1], a23.y, b1, acc2[3][1]);
            FMA_F32X2(acc2[3][2], a23.y, b2, acc2[3][2]);
            FMA_F32X2(acc2[3][3], a23.y, b3, acc2[3][3]);
        }
    }

    float4 bvv = *(const float4*)&bs[4 * tx];
    #pragma unroll
    for (int p = 0; p < 4; p++) {
        float4 vlo, vhi;
        UNPACK_F32X2(vlo.x, vhi.x, acc2[p][0]);
        UNPACK_F32X2(vlo.y, vhi.y, acc2[p][1]);
        UNPACK_F32X2(vlo.z, vhi.z, acc2[p][2]);
        UNPACK_F32X2(vlo.w, vhi.w, acc2[p][3]);
        int r0 = row0 + 8 * ty + 2 * p;
        if (r0 < n_nodes) {
            *(float4*)&g_hw[(size_t)r0 * F_OUT + 4 * tx] = vlo;
            *(float4*)&out[(size_t)r0 * F_OUT + 4 * tx] = bvv;
        }
        if (r0 + 1 < n_nodes) {
            *(float4*)&g_hw[(size_t)(r0 + 1) * F_OUT + 4 * tx] = vhi;
            *(float4*)&out[(size_t)(r0 + 1) * F_OUT + 4 * tx] = bvv;
        }
    }
}

// ---------------------------------------------------------------------------
// Kernel 2: edge phase (round-3 config: 4 edges/warp, 2 per 16-lane group —
// the measured optimum: 2x MLP at 84% occupancy). softmax w/o max-sub,
// multiply gathered hw[src], red.v4 into out[dst]. ef streamed with __ldcs.
// ---------------------------------------------------------------------------
__global__ void edge_kernel(const float* __restrict__ ef,
                            const int* __restrict__ src,
                            const int* __restrict__ dst,
                            float* __restrict__ out,
                            int n_edges) {
    int gw   = (blockIdx.x * blockDim.x + threadIdx.x) >> 5;
    int lane = threadIdx.x & 31;
    int grp  = lane >> 4;
    int sl   = lane & 15;

    int eA = 4 * gw + grp;
    int eB = eA + 2;
    bool vA = (eA < n_edges), vB = (eB < n_edges);
    int ecA = vA ? eA : 0;
    int ecB = vB ? eB : 0;

    int siA = __ldg(src + ecA), diA = __ldg(dst + ecA);
    int siB = __ldg(src + ecB), diB = __ldg(dst + ecB);

    const float4* ef4 = (const float4*)ef;
    float4 a = __ldcs(ef4 + (size_t)ecA * (F_OUT / 4) + sl);
    float4 b = __ldcs(ef4 + (size_t)ecB * (F_OUT / 4) + sl);

    const float4* hw4 = (const float4*)g_hw;
    float4 hA = __ldg(hw4 + (size_t)siA * (F_OUT / 4) + sl);
    float4 hB = __ldg(hw4 + (size_t)siB * (F_OUT / 4) + sl);

    float a0 = __expf(a.x), a1 = __expf(a.y), a2 = __expf(a.z), a3 = __expf(a.w);
    float b0 = __expf(b.x), b1 = __expf(b.y), b2 = __expf(b.z), b3 = __expf(b.w);
    float sA = a0 + a1 + a2 + a3;
    float sB = b0 + b1 + b2 + b3;
    #pragma unroll
    for (int o = 8; o; o >>= 1) {
        sA += __shfl_xor_sync(0xffffffffu, sA, o);
        sB += __shfl_xor_sync(0xffffffffu, sB, o);
    }
    float iA = __fdividef(1.0f, sA);
    float iB = __fdividef(1.0f, sB);

    if (vA) {
        float* p = out + (size_t)diA * F_OUT + 4 * sl;
        asm volatile("red.global.add.v4.f32 [%0], {%1, %2, %3, %4};"
                     :: "l"(p), "f"(hA.x * a0 * iA), "f"(hA.y * a1 * iA),
                        "f"(hA.z * a2 * iA), "f"(hA.w * a3 * iA) : "memory");
    }
    if (vB) {
        float* p = out + (size_t)diB * F_OUT + 4 * sl;
        asm volatile("red.global.add.v4.f32 [%0], {%1, %2, %3, %4};"
                     :: "l"(p), "f"(hB.x * b0 * iB), "f"(hB.y * b1 * iB),
                        "f"(hB.z * b2 * iB), "f"(hB.w * b3 * iB) : "memory");
    }
}

// ---------------------------------------------------------------------------
extern "C" void kernel_launch(void* const* d_in, const int* in_sizes, int n_in,
                              void* d_out, int out_size) {
    const float* h    = (const float*)d_in[0];
    const float* ef   = (const float*)d_in[1];
    const float* w    = (const float*)d_in[2];
    const float* bias = (const float*)d_in[3];
    const int*   src  = (const int*)d_in[4];
    const int*   dst  = (const int*)d_in[5];
    float* out = (float*)d_out;

    int n_nodes = in_sizes[0] / F_IN;
    int n_edges = in_sizes[4];

    gemm_init_kernel<<<(n_nodes + GR - 1) / GR, 128>>>(h, w, bias, out, n_nodes);

    int warps  = (n_edges + 3) / 4;
    int blocks = (warps * 32 + 255) / 256;
    edge_kernel<<<blocks, 256>>>(ef, src, dst, out, n_edges);
}

// round 8
// speedup vs baseline: 1.1791x; 1.1791x over previous
#include <cuda_runtime.h>
#include <cuda_bf16.h>
#include <cstdint>

#define F_IN 128
#define F_OUT 64
#define MAX_NODES 50000

// Scratch (no runtime allocation allowed)
__device__ float g_hw[(size_t)MAX_NODES * F_OUT]; // h @ (W0+W1), [N][64]

// ---------------------------------------------------------------------------
// TF32 helpers
// ---------------------------------------------------------------------------
__device__ __forceinline__ unsigned cvt_tf32(float x) {
    unsigned r;
    asm("cvt.rna.tf32.f32 %0, %1;" : "=r"(r) : "f"(x));
    return r;
}

// D(16x8,f32) += A(16x8,tf32,row) * B(8x8,tf32,col)
#define MMA_TF32(d, a0, a1, a2, a3, b0, b1)                                  \
    asm("mma.sync.aligned.m16n8k8.row.col.f32.tf32.tf32.f32 "                \
        "{%0,%1,%2,%3}, {%4,%5,%6,%7}, {%8,%9}, {%0,%1,%2,%3};"              \
        : "+f"(d[0]), "+f"(d[1]), "+f"(d[2]), "+f"(d[3])                     \
        : "r"(a0), "r"(a1), "r"(a2), "r"(a3), "r"(b0), "r"(b1))

// ---------------------------------------------------------------------------
// Kernel 1: fused TF32 tensor-core GEMM + bias-init (3xTF32 for fp32 accuracy)
//   g_hw[N,64] = h[N,128] @ (W0+W1) ;  out[N,64] = bias
// Block: 64 rows x 64 cols, 128 threads (4 warps), warp w -> rows 16w..16w+15.
// K chunked by 32; W0+W1 split into tf32 hi/lo during staging.
// smem bank math: hs stride 36 -> A-frag LDS banks 4g+t (all 32 distinct);
//                 wh/wl stride 72 (== 8 mod 32) -> B-frag banks 8t+g distinct.
// ---------------------------------------------------------------------------
#define GR 64
#define KC 32
#define HS_S 36
#define WS_S 72
__global__ void __launch_bounds__(128) gemm_tc_kernel(
        const float* __restrict__ h,
        const float* __restrict__ w,
        const float* __restrict__ bias,
        float* __restrict__ out,
        int n_nodes) {
    __shared__ __align__(16) float hs[GR][HS_S];   // 9.2 KB: A chunk [row][k]
    __shared__ __align__(16) float wh[KC][WS_S];   // 9.2 KB: Wsum hi [k][n]
    __shared__ __align__(16) float wl[KC][WS_S];   // 9.2 KB: Wsum lo [k][n]
    __shared__ __align__(16) float bs[F_OUT];

    int tid  = threadIdx.x;
    int lane = tid & 31;
    int warp = tid >> 5;
    int g = lane >> 2;      // groupID (0..7)
    int t = lane & 3;       // thread-in-group (0..3)
    int row0 = blockIdx.x * GR;
    int wr0  = warp * 16;   // warp's row offset within tile

    if (tid < F_OUT) bs[tid] = bias[tid];

    float acc[8][4];        // 8 n-tiles x 4 accum regs
    #pragma unroll
    for (int nt = 0; nt < 8; nt++)
        #pragma unroll
        for (int i = 0; i < 4; i++) acc[nt][i] = 0.0f;

    #pragma unroll
    for (int chunk = 0; chunk < F_IN / KC; chunk++) {
        int k0 = chunk * KC;
        __syncthreads();    // previous chunk's consumers done (1st iter: bs)

        // Stage A chunk: 64 rows x 32 k  (512 float4 loads, scalar stores)
        #pragma unroll
        for (int i = tid; i < GR * (KC / 4); i += 128) {
            int r = i >> 3;         // row (KC/4 = 8 float4 per row)
            int c = i & 7;          // float4 idx within row
            float4 v = make_float4(0.f, 0.f, 0.f, 0.f);
            if (row0 + r < n_nodes)
                v = ((const float4*)(h + (size_t)(row0 + r) * F_IN + k0))[c];
            hs[r][4 * c + 0] = v.x;
            hs[r][4 * c + 1] = v.y;
            hs[r][4 * c + 2] = v.z;
            hs[r][4 * c + 3] = v.w;
        }

        // Stage W chunk: wsum = W0+W1, split hi/lo  (KC*64 = 2048 elems)
        #pragma unroll
        for (int i = tid; i < KC * (F_OUT / 4); i += 128) {
            int k = i >> 4;         // k within chunk (16 float4 per k-row)
            int q = i & 15;         // float4 idx
            const float4* w0 = (const float4*)(w + (size_t)(k0 + k) * F_OUT);
            const float4* w1 = (const float4*)(w + (size_t)F_IN * F_OUT + (size_t)(k0 + k) * F_OUT);
            float4 s0 = w0[q], s1 = w1[q];
            float s[4] = {s0.x + s1.x, s0.y + s1.y, s0.z + s1.z, s0.w + s1.w};
            #pragma unroll
            for (int j = 0; j < 4; j++) {
                float hi = __uint_as_float(cvt_tf32(s[j]));
                wh[k][4 * q + j] = hi;
                wl[k][4 * q + j] = s[j] - hi;
            }
        }
        __syncthreads();

        // Compute: 4 k-steps of 8
        #pragma unroll
        for (int ks = 0; ks < KC; ks += 8) {
            float af0 = hs[wr0 + g][ks + t];
            float af1 = hs[wr0 + g + 8][ks + t];
            float af2 = hs[wr0 + g][ks + t + 4];
            float af3 = hs[wr0 + g + 8][ks + t + 4];
            unsigned ah0 = cvt_tf32(af0), ah1 = cvt_tf32(af1);
            unsigned ah2 = cvt_tf32(af2), ah3 = cvt_tf32(af3);
            unsigned al0 = __float_as_uint(af0 - __uint_as_float(ah0));
            unsigned al1 = __float_as_uint(af1 - __uint_as_float(ah1));
            unsigned al2 = __float_as_uint(af2 - __uint_as_float(ah2));
            unsigned al3 = __float_as_uint(af3 - __uint_as_float(ah3));

            #pragma unroll
            for (int nt = 0; nt < 8; nt++) {
                int n = 8 * nt + g;
                unsigned bh0 = __float_as_uint(wh[ks + t][n]);
                unsigned bh1 = __float_as_uint(wh[ks + t + 4][n]);
                unsigned bl0 = __float_as_uint(wl[ks + t][n]);
                unsigned bl1 = __float_as_uint(wl[ks + t + 4][n]);
                MMA_TF32(acc[nt], ah0, ah1, ah2, ah3, bh0, bh1);
                MMA_TF32(acc[nt], ah0, ah1, ah2, ah3, bl0, bl1);
                MMA_TF32(acc[nt], al0, al1, al2, al3, bh0, bh1);
            }
        }
    }

    // Write D -> g_hw and bias -> out. c0/c1 at (g, 2t..), c2/c3 at (g+8, ..)
    int r1 = row0 + wr0 + g;
    int r2 = r1 + 8;
    #pragma unroll
    for (int nt = 0; nt < 8; nt++) {
        int c = 8 * nt + 2 * t;
        float2 bv = make_float2(bs[c], bs[c + 1]);
        if (r1 < n_nodes) {
            *(float2*)&g_hw[(size_t)r1 * F_OUT + c] = make_float2(acc[nt][0], acc[nt][1]);
            *(float2*)&out[(size_t)r1 * F_OUT + c] = bv;
        }
        if (r2 < n_nodes) {
            *(float2*)&g_hw[(size_t)r2 * F_OUT + c] = make_float2(acc[nt][2], acc[nt][3]);
            *(float2*)&out[(size_t)r2 * F_OUT + c] = bv;
        }
    }
}

// ---------------------------------------------------------------------------
// Kernel 2: edge phase (measured optimum: 4 edges/warp, 2 per 16-lane group,
// 2x MLP at ~84% occupancy). softmax w/o max-sub (O(1) inputs), multiply
// gathered hw[src], red.v4 into out[dst]. ef streamed with __ldcs.
// ---------------------------------------------------------------------------
__global__ void edge_kernel(const float* __restrict__ ef,
                            const int* __restrict__ src,
                            const int* __restrict__ dst,
                            float* __restrict__ out,
                            int n_edges) {
    int gw   = (blockIdx.x * blockDim.x + threadIdx.x) >> 5;
    int lane = threadIdx.x & 31;
    int grp  = lane >> 4;
    int sl   = lane & 15;

    int eA = 4 * gw + grp;
    int eB = eA + 2;
    bool vA = (eA < n_edges), vB = (eB < n_edges);
    int ecA = vA ? eA : 0;
    int ecB = vB ? eB : 0;

    int siA = __ldg(src + ecA), diA = __ldg(dst + ecA);
    int siB = __ldg(src + ecB), diB = __ldg(dst + ecB);

    const float4* ef4 = (const float4*)ef;
    float4 a = __ldcs(ef4 + (size_t)ecA * (F_OUT / 4) + sl);
    float4 b = __ldcs(ef4 + (size_t)ecB * (F_OUT / 4) + sl);

    const float4* hw4 = (const float4*)g_hw;
    float4 hA = __ldg(hw4 + (size_t)siA * (F_OUT / 4) + sl);
    float4 hB = __ldg(hw4 + (size_t)siB * (F_OUT / 4) + sl);

    float a0 = __expf(a.x), a1 = __expf(a.y), a2 = __expf(a.z), a3 = __expf(a.w);
    float b0 = __expf(b.x), b1 = __expf(b.y), b2 = __expf(b.z), b3 = __expf(b.w);
    float sA = a0 + a1 + a2 + a3;
    float sB = b0 + b1 + b2 + b3;
    #pragma unroll
    for (int o = 8; o; o >>= 1) {
        sA += __shfl_xor_sync(0xffffffffu, sA, o);
        sB += __shfl_xor_sync(0xffffffffu, sB, o);
    }
    float iA = __fdividef(1.0f, sA);
    float iB = __fdividef(1.0f, sB);

    if (vA) {
        float* p = out + (size_t)diA * F_OUT + 4 * sl;
        asm volatile("red.global.add.v4.f32 [%0], {%1, %2, %3, %4};"
                     :: "l"(p), "f"(hA.x * a0 * iA), "f"(hA.y * a1 * iA),
                        "f"(hA.z * a2 * iA), "f"(hA.w * a3 * iA) : "memory");
    }
    if (vB) {
        float* p = out + (size_t)diB * F_OUT + 4 * sl;
        asm volatile("red.global.add.v4.f32 [%0], {%1, %2, %3, %4};"
                     :: "l"(p), "f"(hB.x * b0 * iB), "f"(hB.y * b1 * iB),
                        "f"(hB.z * b2 * iB), "f"(hB.w * b3 * iB) : "memory");
    }
}

// ---------------------------------------------------------------------------
extern "C" void kernel_launch(void* const* d_in, const int* in_sizes, int n_in,
                              void* d_out, int out_size) {
    const float* h    = (const float*)d_in[0];
    const float* ef   = (const float*)d_in[1];
    const float* w    = (const float*)d_in[2];
    const float* bias = (const float*)d_in[3];
    const int*   src  = (const int*)d_in[4];
    const int*   dst  = (const int*)d_in[5];
    float* out = (float*)d_out;

    int n_nodes = in_sizes[0] / F_IN;
    int n_edges = in_sizes[4];

    gemm_tc_kernel<<<(n_nodes + GR - 1) / GR, 128>>>(h, w, bias, out, n_nodes);

    int warps  = (n_edges + 3) / 4;
    int blocks = (warps * 32 + 255) / 256;
    edge_kernel<<<blocks, 256>>>(ef, src, dst, out, n_edges);
}